// round 1
// baseline (speedup 1.0000x reference)
#include <cuda_runtime.h>
#include <cuda_bf16.h>
#include <cstdint>

// Problem constants
#define GH 8
#define GW 8
#define RR 64          // regions
#define BB 8           // batch
#define CIN 128
#define COUT 256
#define TH 32          // tile h
#define TW 32          // tile w
#define NPIX 1024      // TH*TW
#define NN 8192        // BB*NPIX  (GEMM N per region)
#define KK 256         // CIN*2    (GEMM K per region: [gelu(y); x])
#define EPSV 1e-5f

// ---------------- scratch (device globals; no runtime allocation) -------------
// S: per-region stacked operand, layout [r][k][n], k in [0,256): k<128 -> gelu path, k>=128 -> raw x
__device__ float g_S[(size_t)RR * KK * NN];          // 512 MB
// Folded weight: [r][o][k], k<128 -> sc2*pw_w, k>=128 -> res_w
__device__ float g_W[(size_t)RR * COUT * KK];        // 16 MB
__device__ float g_bias[RR * COUT];                  // sh2

// ---------------- kernel 0: fold BN2 into weights -----------------------------
__global__ __launch_bounds__(256) void k_prep(const float* __restrict__ pw_w,
                                              const float* __restrict__ res_w,
                                              const float* __restrict__ g2,
                                              const float* __restrict__ b2,
                                              const float* __restrict__ m2,
                                              const float* __restrict__ v2) {
    int idx = blockIdx.x * 256 + threadIdx.x;           // over RR*COUT*KK = 4.19M
    int r = idx >> 16;                                  // /65536
    int rem = idx & 65535;
    int o = rem >> 8;
    int k = rem & 255;
    int ro = r * COUT + o;
    float rs = rsqrtf(v2[ro] + EPSV);
    float sc = g2[ro] * rs;
    float wv;
    if (k < CIN) wv = sc * pw_w[(size_t)ro * CIN + k];
    else         wv = res_w[(size_t)ro * CIN + (k - CIN)];
    g_W[idx] = wv;
    if (k == 0) g_bias[ro] = b2[ro] - g2[ro] * m2[ro] * rs;
}

// ---------------- kernel 1: depthwise 3x3 + BN1 + exact GELU, build S ---------
__global__ __launch_bounds__(256) void k_dw(const float* __restrict__ x,
                                            const float* __restrict__ dw_w,
                                            const float* __restrict__ g1,
                                            const float* __restrict__ b1,
                                            const float* __restrict__ m1,
                                            const float* __restrict__ v1) {
    __shared__ float t[TH][TW];
    int bid = blockIdx.x;                 // RR*BB*CIN = 65536 blocks
    int c  = bid & 127;
    int bb = (bid >> 7) & 7;
    int r  = bid >> 10;
    int gh = r >> 3, gw = r & 7;
    int tid = threadIdx.x;

    const float* xp = x + (((size_t)(bb * CIN + c) * 256 + gh * TH) * 256 + gw * TW);
    #pragma unroll
    for (int p = tid; p < NPIX; p += 256) {
        int row = p >> 5, col = p & 31;
        t[row][col] = xp[(size_t)row * 256 + col];
    }

    float w[9];
    const float* wp = dw_w + (size_t)(r * CIN + c) * 9;
    #pragma unroll
    for (int i = 0; i < 9; i++) w[i] = wp[i];

    int rc = r * CIN + c;
    float rs = rsqrtf(v1[rc] + EPSV);
    float sc = g1[rc] * rs;
    float sh = b1[rc] - g1[rc] * m1[rc] * rs;

    __syncthreads();

    size_t base  = ((size_t)(r * KK + c)) * NN + (size_t)bb * NPIX;
    size_t basex = ((size_t)(r * KK + CIN + c)) * NN + (size_t)bb * NPIX;

    #pragma unroll
    for (int p = tid; p < NPIX; p += 256) {
        int row = p >> 5, col = p & 31;
        float s = 0.f;
        #pragma unroll
        for (int dr = -1; dr <= 1; dr++) {
            #pragma unroll
            for (int dc = -1; dc <= 1; dc++) {
                int rr2 = row + dr, cc2 = col + dc;
                float vv = (rr2 >= 0 && rr2 < TH && cc2 >= 0 && cc2 < TW) ? t[rr2][cc2] : 0.f;
                s = fmaf(vv, w[(dr + 1) * 3 + (dc + 1)], s);
            }
        }
        float yv = fmaf(s, sc, sh);
        float gv = yv * normcdff(yv);        // exact GELU: x * Phi(x)
        g_S[base + p]  = gv;
        g_S[basex + p] = t[row][col];
    }
}

// ---------------- kernel 2: per-region GEMM + bias + reassembly ---------------
// C[r][o][n] = sum_k W[r][o][k] * S[r][k][n] + bias[r][o]
// out[b][o][gh*32+prow][gw*32+pcol],  n = b*1024 + prow*32 + pcol
#define BM 128
#define BN 128
#define BKS 8

__global__ __launch_bounds__(256) void k_gemm(float* __restrict__ out) {
    __shared__ float As[BKS][BM + 4];
    __shared__ float Bs[BKS][BN];

    int r  = blockIdx.z;
    int m0 = blockIdx.y * BM;
    int n0 = blockIdx.x * BN;
    const float* A = g_W + (size_t)r * COUT * KK;
    const float* Bm = g_S + (size_t)r * KK * NN;

    int tid = threadIdx.x;
    int tx = tid & 15, ty = tid >> 4;

    // A-tile load mapping: row = tid>>1 (0..127), 4 consecutive k at (tid&1)*4
    int a_row = tid >> 1;
    int a_k4  = (tid & 1) * 4;
    // B-tile load mapping: krow = tid>>5 (0..7), 4 consecutive n at (tid&31)*4
    int b_kr  = tid >> 5;
    int b_n4  = (tid & 31) * 4;

    float acc[8][8];
    #pragma unroll
    for (int i = 0; i < 8; i++)
        #pragma unroll
        for (int j = 0; j < 8; j++) acc[i][j] = 0.f;

    for (int k0 = 0; k0 < KK; k0 += BKS) {
        float4 av = *(const float4*)&A[(size_t)(m0 + a_row) * KK + k0 + a_k4];
        As[a_k4 + 0][a_row] = av.x;
        As[a_k4 + 1][a_row] = av.y;
        As[a_k4 + 2][a_row] = av.z;
        As[a_k4 + 3][a_row] = av.w;
        float4 bv = *(const float4*)&Bm[(size_t)(k0 + b_kr) * NN + n0 + b_n4];
        *(float4*)&Bs[b_kr][b_n4] = bv;
        __syncthreads();

        #pragma unroll
        for (int kk = 0; kk < BKS; kk++) {
            float4 a0 = *(const float4*)&As[kk][ty * 8];
            float4 a1 = *(const float4*)&As[kk][ty * 8 + 4];
            float4 c0 = *(const float4*)&Bs[kk][tx * 8];
            float4 c1 = *(const float4*)&Bs[kk][tx * 8 + 4];
            float ar[8] = {a0.x, a0.y, a0.z, a0.w, a1.x, a1.y, a1.z, a1.w};
            float br[8] = {c0.x, c0.y, c0.z, c0.w, c1.x, c1.y, c1.z, c1.w};
            #pragma unroll
            for (int i = 0; i < 8; i++)
                #pragma unroll
                for (int j = 0; j < 8; j++)
                    acc[i][j] = fmaf(ar[i], br[j], acc[i][j]);
        }
        __syncthreads();
    }

    // epilogue: bias + scatter back into [B, COUT, 256, 256]
    int gh = r >> 3, gw = r & 7;
    int n_base = n0 + tx * 8;
    int b_idx  = n_base >> 10;
    int hw     = n_base & 1023;
    int prow   = hw >> 5, pcol = hw & 31;

    #pragma unroll
    for (int i = 0; i < 8; i++) {
        int mo = m0 + ty * 8 + i;
        float bi = g_bias[r * COUT + mo];
        size_t ooff = (((size_t)(b_idx * COUT + mo) * 256 + gh * TH + prow) * 256 + gw * TW + pcol);
        float4 v0 = make_float4(acc[i][0] + bi, acc[i][1] + bi, acc[i][2] + bi, acc[i][3] + bi);
        float4 v1 = make_float4(acc[i][4] + bi, acc[i][5] + bi, acc[i][6] + bi, acc[i][7] + bi);
        *(float4*)&out[ooff]     = v0;
        *(float4*)&out[ooff + 4] = v1;
    }
}

// ---------------- launch ------------------------------------------------------
extern "C" void kernel_launch(void* const* d_in, const int* in_sizes, int n_in,
                              void* d_out, int out_size) {
    const float* x     = (const float*)d_in[0];
    const float* dw_w  = (const float*)d_in[1];
    const float* bn1_g = (const float*)d_in[2];
    const float* bn1_b = (const float*)d_in[3];
    const float* bn1_m = (const float*)d_in[4];
    const float* bn1_v = (const float*)d_in[5];
    const float* pw_w  = (const float*)d_in[6];
    const float* bn2_g = (const float*)d_in[7];
    const float* bn2_b = (const float*)d_in[8];
    const float* bn2_m = (const float*)d_in[9];
    const float* bn2_v = (const float*)d_in[10];
    const float* res_w = (const float*)d_in[11];
    float* out = (float*)d_out;

    // fold BN2 into GEMM weights + bias
    k_prep<<<(RR * COUT * KK) / 256, 256>>>(pw_w, res_w, bn2_g, bn2_b, bn2_m, bn2_v);
    // depthwise + BN1 + GELU, build stacked operand S
    k_dw<<<RR * BB * CIN, 256>>>(x, dw_w, bn1_g, bn1_b, bn1_m, bn1_v);
    // batched per-region GEMM + bias + reassembly
    dim3 grid(NN / BN, COUT / BM, RR);
    k_gemm<<<grid, 256>>>(out);
}

// round 2
// speedup vs baseline: 1.0016x; 1.0016x over previous
#include <cuda_runtime.h>
#include <cuda_bf16.h>
#include <cstdint>

// Problem constants
#define GH 8
#define GW 8
#define RR 64          // regions
#define BB 8           // batch
#define CIN 128
#define COUT 256
#define TH 32          // tile h
#define TW 32          // tile w
#define NPIX 1024      // TH*TW
#define NN 8192        // BB*NPIX  (GEMM N per region)
#define KK 256         // CIN*2    (GEMM K per region: [gelu(y); x])
#define EPSV 1e-5f

// ---------------- scratch (device globals; no runtime allocation) -------------
// S: per-region stacked operand, layout [r][k][n], k in [0,256): k<128 -> gelu path, k>=128 -> raw x
__device__ float g_S[(size_t)RR * KK * NN];          // 512 MB
// Folded weight: [r][o][k], k<128 -> sc2*pw_w, k>=128 -> res_w
__device__ float g_W[(size_t)RR * COUT * KK];        // 16 MB
__device__ float g_bias[RR * COUT];                  // sh2

// ---------------- kernel 0: fold BN2 into weights -----------------------------
__global__ __launch_bounds__(256) void k_prep(const float* __restrict__ pw_w,
                                              const float* __restrict__ res_w,
                                              const float* __restrict__ g2,
                                              const float* __restrict__ b2,
                                              const float* __restrict__ m2,
                                              const float* __restrict__ v2) {
    int idx = blockIdx.x * 256 + threadIdx.x;           // over RR*COUT*KK = 4.19M
    int r = idx >> 16;                                  // /65536
    int rem = idx & 65535;
    int o = rem >> 8;
    int k = rem & 255;
    int ro = r * COUT + o;
    float rs = rsqrtf(v2[ro] + EPSV);
    float sc = g2[ro] * rs;
    float wv;
    if (k < CIN) wv = sc * pw_w[(size_t)ro * CIN + k];
    else         wv = res_w[(size_t)ro * CIN + (k - CIN)];
    g_W[idx] = wv;
    if (k == 0) g_bias[ro] = b2[ro] - g2[ro] * m2[ro] * rs;
}

// ---------------- kernel 1: depthwise 3x3 + BN1 + exact GELU, build S ---------
__global__ __launch_bounds__(256) void k_dw(const float* __restrict__ x,
                                            const float* __restrict__ dw_w,
                                            const float* __restrict__ g1,
                                            const float* __restrict__ b1,
                                            const float* __restrict__ m1,
                                            const float* __restrict__ v1) {
    __shared__ float t[TH][TW];
    int bid = blockIdx.x;                 // RR*BB*CIN = 65536 blocks
    int c  = bid & 127;
    int bb = (bid >> 7) & 7;
    int r  = bid >> 10;
    int gh = r >> 3, gw = r & 7;
    int tid = threadIdx.x;

    const float* xp = x + (((size_t)(bb * CIN + c) * 256 + gh * TH) * 256 + gw * TW);
    #pragma unroll
    for (int p = tid; p < NPIX; p += 256) {
        int row = p >> 5, col = p & 31;
        t[row][col] = xp[(size_t)row * 256 + col];
    }

    float w[9];
    const float* wp = dw_w + (size_t)(r * CIN + c) * 9;
    #pragma unroll
    for (int i = 0; i < 9; i++) w[i] = wp[i];

    int rc = r * CIN + c;
    float rs = rsqrtf(v1[rc] + EPSV);
    float sc = g1[rc] * rs;
    float sh = b1[rc] - g1[rc] * m1[rc] * rs;

    __syncthreads();

    size_t base  = ((size_t)(r * KK + c)) * NN + (size_t)bb * NPIX;
    size_t basex = ((size_t)(r * KK + CIN + c)) * NN + (size_t)bb * NPIX;

    #pragma unroll
    for (int p = tid; p < NPIX; p += 256) {
        int row = p >> 5, col = p & 31;
        float s = 0.f;
        #pragma unroll
        for (int dr = -1; dr <= 1; dr++) {
            #pragma unroll
            for (int dc = -1; dc <= 1; dc++) {
                int rr2 = row + dr, cc2 = col + dc;
                float vv = (rr2 >= 0 && rr2 < TH && cc2 >= 0 && cc2 < TW) ? t[rr2][cc2] : 0.f;
                s = fmaf(vv, w[(dr + 1) * 3 + (dc + 1)], s);
            }
        }
        float yv = fmaf(s, sc, sh);
        float gv = yv * normcdff(yv);        // exact GELU: x * Phi(x)
        g_S[base + p]  = gv;
        g_S[basex + p] = t[row][col];
    }
}

// ---------------- kernel 2: per-region GEMM + bias + reassembly ---------------
// C[r][o][n] = sum_k W[r][o][k] * S[r][k][n] + bias[r][o]
// out[b][o][gh*32+prow][gw*32+pcol],  n = b*1024 + prow*32 + pcol
#define BM 128
#define BN 128
#define BKS 8

__global__ __launch_bounds__(256) void k_gemm(float* __restrict__ out) {
    __shared__ float As[BKS][BM + 4];
    __shared__ float Bs[BKS][BN];

    int r  = blockIdx.z;
    int m0 = blockIdx.y * BM;
    int n0 = blockIdx.x * BN;
    const float* A = g_W + (size_t)r * COUT * KK;
    const float* Bm = g_S + (size_t)r * KK * NN;

    int tid = threadIdx.x;
    int tx = tid & 15, ty = tid >> 4;

    // A-tile load mapping: row = tid>>1 (0..127), 4 consecutive k at (tid&1)*4
    int a_row = tid >> 1;
    int a_k4  = (tid & 1) * 4;
    // B-tile load mapping: krow = tid>>5 (0..7), 4 consecutive n at (tid&31)*4
    int b_kr  = tid >> 5;
    int b_n4  = (tid & 31) * 4;

    float acc[8][8];
    #pragma unroll
    for (int i = 0; i < 8; i++)
        #pragma unroll
        for (int j = 0; j < 8; j++) acc[i][j] = 0.f;

    for (int k0 = 0; k0 < KK; k0 += BKS) {
        float4 av = *(const float4*)&A[(size_t)(m0 + a_row) * KK + k0 + a_k4];
        As[a_k4 + 0][a_row] = av.x;
        As[a_k4 + 1][a_row] = av.y;
        As[a_k4 + 2][a_row] = av.z;
        As[a_k4 + 3][a_row] = av.w;
        float4 bv = *(const float4*)&Bm[(size_t)(k0 + b_kr) * NN + n0 + b_n4];
        *(float4*)&Bs[b_kr][b_n4] = bv;
        __syncthreads();

        #pragma unroll
        for (int kk = 0; kk < BKS; kk++) {
            float4 a0 = *(const float4*)&As[kk][ty * 8];
            float4 a1 = *(const float4*)&As[kk][ty * 8 + 4];
            float4 c0 = *(const float4*)&Bs[kk][tx * 8];
            float4 c1 = *(const float4*)&Bs[kk][tx * 8 + 4];
            float ar[8] = {a0.x, a0.y, a0.z, a0.w, a1.x, a1.y, a1.z, a1.w};
            float br[8] = {c0.x, c0.y, c0.z, c0.w, c1.x, c1.y, c1.z, c1.w};
            #pragma unroll
            for (int i = 0; i < 8; i++)
                #pragma unroll
                for (int j = 0; j < 8; j++)
                    acc[i][j] = fmaf(ar[i], br[j], acc[i][j]);
        }
        __syncthreads();
    }

    // epilogue: bias + scatter back into [B, COUT, 256, 256]
    int gh = r >> 3, gw = r & 7;
    int n_base = n0 + tx * 8;
    int b_idx  = n_base >> 10;
    int hw     = n_base & 1023;
    int prow   = hw >> 5, pcol = hw & 31;

    #pragma unroll
    for (int i = 0; i < 8; i++) {
        int mo = m0 + ty * 8 + i;
        float bi = g_bias[r * COUT + mo];
        size_t ooff = (((size_t)(b_idx * COUT + mo) * 256 + gh * TH + prow) * 256 + gw * TW + pcol);
        float4 v0 = make_float4(acc[i][0] + bi, acc[i][1] + bi, acc[i][2] + bi, acc[i][3] + bi);
        float4 v1 = make_float4(acc[i][4] + bi, acc[i][5] + bi, acc[i][6] + bi, acc[i][7] + bi);
        *(float4*)&out[ooff]     = v0;
        *(float4*)&out[ooff + 4] = v1;
    }
}

// ---------------- launch ------------------------------------------------------
extern "C" void kernel_launch(void* const* d_in, const int* in_sizes, int n_in,
                              void* d_out, int out_size) {
    const float* x     = (const float*)d_in[0];
    const float* dw_w  = (const float*)d_in[1];
    const float* bn1_g = (const float*)d_in[2];
    const float* bn1_b = (const float*)d_in[3];
    const float* bn1_m = (const float*)d_in[4];
    const float* bn1_v = (const float*)d_in[5];
    const float* pw_w  = (const float*)d_in[6];
    const float* bn2_g = (const float*)d_in[7];
    const float* bn2_b = (const float*)d_in[8];
    const float* bn2_m = (const float*)d_in[9];
    const float* bn2_v = (const float*)d_in[10];
    const float* res_w = (const float*)d_in[11];
    float* out = (float*)d_out;

    // fold BN2 into GEMM weights + bias
    k_prep<<<(RR * COUT * KK) / 256, 256>>>(pw_w, res_w, bn2_g, bn2_b, bn2_m, bn2_v);
    // depthwise + BN1 + GELU, build stacked operand S
    k_dw<<<RR * BB * CIN, 256>>>(x, dw_w, bn1_g, bn1_b, bn1_m, bn1_v);
    // batched per-region GEMM + bias + reassembly
    dim3 grid(NN / BN, COUT / BM, RR);
    k_gemm<<<grid, 256>>>(out);
}